// round 1
// baseline (speedup 1.0000x reference)
#include <cuda_runtime.h>
#include <math.h>

// Problem constants
#define BN_ 8
#define TN_ 1024
#define CN_ 1024
#define HN_ 16
#define DH_ 64
#define MD_ (BN_ * TN_)      // 8192 rows
#define FFD_ (4 * CN_)       // 4096

// ---------------------------------------------------------------------------
// Scratch (device globals — no allocation allowed)
// ---------------------------------------------------------------------------
__device__ float g_h  [MD_ * CN_];
__device__ float g_q  [MD_ * CN_];
__device__ float g_k  [MD_ * CN_];
__device__ float g_v  [MD_ * CN_];
__device__ float g_ctx[MD_ * CN_];
__device__ float g_x1 [MD_ * CN_];
__device__ float g_h2 [MD_ * CN_];
__device__ float g_ff [MD_ * FFD_];

// ---------------------------------------------------------------------------
// LayerNorm: one block per row of 1024, 256 threads, one float4 per thread
// ---------------------------------------------------------------------------
__global__ __launch_bounds__(256)
void ln_kernel(const float* __restrict__ x, const float* __restrict__ w,
               const float* __restrict__ b, float* __restrict__ out)
{
    const int row = blockIdx.x;
    const int tid = threadIdx.x;
    const float4 v = *(const float4*)(x + (size_t)row * CN_ + tid * 4);

    float s  = v.x + v.y + v.z + v.w;
    float ss = v.x * v.x + v.y * v.y + v.z * v.z + v.w * v.w;
    #pragma unroll
    for (int o = 16; o > 0; o >>= 1) {
        s  += __shfl_xor_sync(0xFFFFFFFFu, s,  o);
        ss += __shfl_xor_sync(0xFFFFFFFFu, ss, o);
    }
    __shared__ float rs[8], rss[8];
    const int wid = tid >> 5, lane = tid & 31;
    if (lane == 0) { rs[wid] = s; rss[wid] = ss; }
    __syncthreads();
    float tot = 0.f, tots = 0.f;
    #pragma unroll
    for (int i = 0; i < 8; i++) { tot += rs[i]; tots += rss[i]; }

    const float mu   = tot * (1.0f / (float)CN_);
    const float var  = tots * (1.0f / (float)CN_) - mu * mu;
    const float rsig = rsqrtf(var + 1e-5f);

    const float4 wv = *(const float4*)(w + tid * 4);
    const float4 bv = *(const float4*)(b + tid * 4);
    float4 o;
    o.x = (v.x - mu) * rsig * wv.x + bv.x;
    o.y = (v.y - mu) * rsig * wv.y + bv.y;
    o.z = (v.z - mu) * rsig * wv.z + bv.z;
    o.w = (v.w - mu) * rsig * wv.w + bv.w;
    *(float4*)(out + (size_t)row * CN_ + tid * 4) = o;
}

// ---------------------------------------------------------------------------
// SGEMM: C[M,N] = A[M,K] @ W[K,N] + bias (+ gelu) (+ residual)
// 128x128 block tile, BK=8, 256 threads, 8x8 per thread.
// All dims are multiples of 128 / 8 here, so no bounds checks.
// ---------------------------------------------------------------------------
__device__ __forceinline__ float gelu_exact(float x)
{
    return 0.5f * x * (1.0f + erff(x * 0.70710678118654752f));
}

__global__ __launch_bounds__(256, 2)
void gemm_kernel(const float* __restrict__ A, const float* __restrict__ W,
                 const float* __restrict__ bias, const float* __restrict__ res,
                 float* __restrict__ C, int M, int N, int K, int act)
{
    __shared__ float sA[8][128];   // transposed A tile: sA[k][m]
    __shared__ float sB[8][128];   // sB[k][n]

    const int tid = threadIdx.x;
    const int bm = blockIdx.y * 128;
    const int bn = blockIdx.x * 128;
    const int ty = tid >> 4;       // 0..15
    const int tx = tid & 15;       // 0..15

    const int a_row = tid >> 1;          // 0..127
    const int a_col = (tid & 1) * 4;     // 0 or 4
    const int b_row = tid >> 5;          // 0..7
    const int b_col = (tid & 31) * 4;    // 0..124

    const float* Aptr = A + (size_t)(bm + a_row) * K + a_col;
    const float* Wptr = W + (size_t)b_row * N + bn + b_col;

    float acc[8][8];
    #pragma unroll
    for (int i = 0; i < 8; i++)
        #pragma unroll
        for (int j = 0; j < 8; j++) acc[i][j] = 0.f;

    for (int k0 = 0; k0 < K; k0 += 8) {
        const float4 av = *(const float4*)(Aptr + k0);
        const float4 bv = *(const float4*)(Wptr + (size_t)k0 * N);
        sA[a_col + 0][a_row] = av.x;
        sA[a_col + 1][a_row] = av.y;
        sA[a_col + 2][a_row] = av.z;
        sA[a_col + 3][a_row] = av.w;
        *(float4*)&sB[b_row][b_col] = bv;
        __syncthreads();

        #pragma unroll
        for (int k = 0; k < 8; k++) {
            const float4 a0 = *(const float4*)&sA[k][ty * 8];
            const float4 a1 = *(const float4*)&sA[k][ty * 8 + 4];
            const float4 b0 = *(const float4*)&sB[k][tx * 8];
            const float4 b1 = *(const float4*)&sB[k][tx * 8 + 4];
            const float af[8] = {a0.x, a0.y, a0.z, a0.w, a1.x, a1.y, a1.z, a1.w};
            const float bf[8] = {b0.x, b0.y, b0.z, b0.w, b1.x, b1.y, b1.z, b1.w};
            #pragma unroll
            for (int i = 0; i < 8; i++)
                #pragma unroll
                for (int j = 0; j < 8; j++)
                    acc[i][j] += af[i] * bf[j];
        }
        __syncthreads();
    }

    #pragma unroll
    for (int i = 0; i < 8; i++) {
        const int row = bm + ty * 8 + i;
        #pragma unroll
        for (int jv = 0; jv < 2; jv++) {
            const int col = bn + tx * 8 + jv * 4;
            const float4 bb = *(const float4*)(bias + col);
            float4 o;
            o.x = acc[i][jv * 4 + 0] + bb.x;
            o.y = acc[i][jv * 4 + 1] + bb.y;
            o.z = acc[i][jv * 4 + 2] + bb.z;
            o.w = acc[i][jv * 4 + 3] + bb.w;
            if (act) {
                o.x = gelu_exact(o.x); o.y = gelu_exact(o.y);
                o.z = gelu_exact(o.z); o.w = gelu_exact(o.w);
            }
            if (res) {
                const float4 rr = *(const float4*)(res + (size_t)row * N + col);
                o.x += rr.x; o.y += rr.y; o.z += rr.z; o.w += rr.w;
            }
            *(float4*)(C + (size_t)row * N + col) = o;
        }
    }
}

// ---------------------------------------------------------------------------
// Flash attention (causal), fp32.
// Grid: (T/64 query tiles, B*H). Block: 256 threads.
// Thread layout: r = tid/4 (query row within tile), quad = tid%4 owns 16 cols.
// smem: sQ (transposed [d][r]), sKV (K phase transposed [d][c]; V phase [c][d]),
//       sP (transposed [c][r]). 3 * 16 KB = 48 KB.
// ---------------------------------------------------------------------------
__global__ __launch_bounds__(256)
void attn_kernel(const float* __restrict__ q, const float* __restrict__ k,
                 const float* __restrict__ v, float* __restrict__ out)
{
    __shared__ float sQ [64][64];
    __shared__ float sKV[64][64];
    __shared__ float sP [64][64];

    const int qt  = blockIdx.x;          // 0..15
    const int bh  = blockIdx.y;          // 0..127
    const int b   = bh >> 4;
    const int h   = bh & 15;
    const int tid = threadIdx.x;
    const int r    = tid >> 2;           // 0..63
    const int quad = tid & 3;
    const int j0   = quad * 16;

    const size_t headoff = (size_t)h * DH_;
    const float* qbase = q + ((size_t)b * TN_ + qt * 64) * CN_ + headoff;

    // Load Q transposed: sQ[d][row]
    #pragma unroll
    for (int it = 0; it < 4; it++) {
        const int idx = tid + it * 256;       // float4 index 0..1023
        const int row = idx >> 4;
        const int c4  = (idx & 15) * 4;
        const float4 val = *(const float4*)(qbase + (size_t)row * CN_ + c4);
        sQ[c4 + 0][row] = val.x;
        sQ[c4 + 1][row] = val.y;
        sQ[c4 + 2][row] = val.z;
        sQ[c4 + 3][row] = val.w;
    }

    float m = -1e30f, l = 0.f;
    float o[16];
    #pragma unroll
    for (int i = 0; i < 16; i++) o[i] = 0.f;

    const float scale = 0.125f;   // 1/sqrt(64)

    for (int kt = 0; kt <= qt; kt++) {
        const float* kbase = k + ((size_t)b * TN_ + kt * 64) * CN_ + headoff;
        const float* vbase = v + ((size_t)b * TN_ + kt * 64) * CN_ + headoff;

        __syncthreads();   // previous iteration's PV reads done
        // Load K transposed: sKV[d][c]
        #pragma unroll
        for (int it = 0; it < 4; it++) {
            const int idx = tid + it * 256;
            const int row = idx >> 4;
            const int c4  = (idx & 15) * 4;
            const float4 val = *(const float4*)(kbase + (size_t)row * CN_ + c4);
            sKV[c4 + 0][row] = val.x;
            sKV[c4 + 1][row] = val.y;
            sKV[c4 + 2][row] = val.z;
            sKV[c4 + 3][row] = val.w;
        }
        __syncthreads();

        // S = Q K^T for this thread's 16 columns
        float s[16];
        #pragma unroll
        for (int i = 0; i < 16; i++) s[i] = 0.f;
        #pragma unroll 16
        for (int kk = 0; kk < 64; kk++) {
            const float qv = sQ[kk][r];
            const float4* kp = (const float4*)&sKV[kk][j0];
            const float4 k0v = kp[0], k1v = kp[1], k2v = kp[2], k3v = kp[3];
            s[0]  += qv * k0v.x; s[1]  += qv * k0v.y; s[2]  += qv * k0v.z; s[3]  += qv * k0v.w;
            s[4]  += qv * k1v.x; s[5]  += qv * k1v.y; s[6]  += qv * k1v.z; s[7]  += qv * k1v.w;
            s[8]  += qv * k2v.x; s[9]  += qv * k2v.y; s[10] += qv * k2v.z; s[11] += qv * k2v.w;
            s[12] += qv * k3v.x; s[13] += qv * k3v.y; s[14] += qv * k3v.z; s[15] += qv * k3v.w;
        }

        // Scale, causal mask (only on diagonal tile), row max
        float tmax = -1e30f;
        const bool diag = (kt == qt);
        #pragma unroll
        for (int i = 0; i < 16; i++) {
            s[i] *= scale;
            if (diag && (j0 + i) > r) s[i] = -1e30f;
            tmax = fmaxf(tmax, s[i]);
        }
        tmax = fmaxf(tmax, __shfl_xor_sync(0xFFFFFFFFu, tmax, 1));
        tmax = fmaxf(tmax, __shfl_xor_sync(0xFFFFFFFFu, tmax, 2));

        const float mnew  = fmaxf(m, tmax);
        const float alpha = __expf(m - mnew);
        float psum = 0.f;
        float p[16];
        #pragma unroll
        for (int i = 0; i < 16; i++) {
            p[i] = __expf(s[i] - mnew);
            psum += p[i];
        }
        psum += __shfl_xor_sync(0xFFFFFFFFu, psum, 1);
        psum += __shfl_xor_sync(0xFFFFFFFFu, psum, 2);
        l = l * alpha + psum;
        m = mnew;
        #pragma unroll
        for (int i = 0; i < 16; i++) o[i] *= alpha;

        // Store P transposed: sP[c][r]
        #pragma unroll
        for (int i = 0; i < 16; i++) sP[j0 + i][r] = p[i];
        __syncthreads();   // S-phase reads of sKV done, P visible

        // Load V row-major into sKV[c][d]
        #pragma unroll
        for (int it = 0; it < 4; it++) {
            const int idx = tid + it * 256;
            const int row = idx >> 4;
            const int c4  = (idx & 15) * 4;
            const float4 val = *(const float4*)(vbase + (size_t)row * CN_ + c4);
            *(float4*)&sKV[row][c4] = val;
        }
        __syncthreads();

        // O += P V
        #pragma unroll 16
        for (int c = 0; c < 64; c++) {
            const float pv = sP[c][r];
            const float4* vp = (const float4*)&sKV[c][j0];
            const float4 v0 = vp[0], v1 = vp[1], v2 = vp[2], v3 = vp[3];
            o[0]  += pv * v0.x; o[1]  += pv * v0.y; o[2]  += pv * v0.z; o[3]  += pv * v0.w;
            o[4]  += pv * v1.x; o[5]  += pv * v1.y; o[6]  += pv * v1.z; o[7]  += pv * v1.w;
            o[8]  += pv * v2.x; o[9]  += pv * v2.y; o[10] += pv * v2.z; o[11] += pv * v2.w;
            o[12] += pv * v3.x; o[13] += pv * v3.y; o[14] += pv * v3.z; o[15] += pv * v3.w;
        }
    }

    const float inv = 1.0f / l;
    float* obase = out + ((size_t)b * TN_ + qt * 64 + r) * CN_ + headoff + j0;
    #pragma unroll
    for (int jv = 0; jv < 4; jv++) {
        float4 ov;
        ov.x = o[jv * 4 + 0] * inv;
        ov.y = o[jv * 4 + 1] * inv;
        ov.z = o[jv * 4 + 2] * inv;
        ov.w = o[jv * 4 + 3] * inv;
        *(float4*)(obase + jv * 4) = ov;
    }
}

// ---------------------------------------------------------------------------
// Launch
// ---------------------------------------------------------------------------
extern "C" void kernel_launch(void* const* d_in, const int* in_sizes, int n_in,
                              void* d_out, int out_size)
{
    const float* x    = (const float*)d_in[0];
    // d_in[1] = mask (int32) — causal, handled analytically
    const float* ln1w = (const float*)d_in[2];
    const float* ln1b = (const float*)d_in[3];
    const float* ln2w = (const float*)d_in[4];
    const float* ln2b = (const float*)d_in[5];
    const float* wq   = (const float*)d_in[6];
    const float* bq   = (const float*)d_in[7];
    const float* wk   = (const float*)d_in[8];
    const float* bk   = (const float*)d_in[9];
    const float* wv   = (const float*)d_in[10];
    const float* bv   = (const float*)d_in[11];
    const float* wo   = (const float*)d_in[12];
    const float* bo   = (const float*)d_in[13];
    const float* w1   = (const float*)d_in[14];
    const float* b1   = (const float*)d_in[15];
    const float* w2   = (const float*)d_in[16];
    const float* b2   = (const float*)d_in[17];
    float* out = (float*)d_out;

    float *h, *q, *k, *v, *ctx, *x1, *h2, *ff;
    cudaGetSymbolAddress((void**)&h,   g_h);
    cudaGetSymbolAddress((void**)&q,   g_q);
    cudaGetSymbolAddress((void**)&k,   g_k);
    cudaGetSymbolAddress((void**)&v,   g_v);
    cudaGetSymbolAddress((void**)&ctx, g_ctx);
    cudaGetSymbolAddress((void**)&x1,  g_x1);
    cudaGetSymbolAddress((void**)&h2,  g_h2);
    cudaGetSymbolAddress((void**)&ff,  g_ff);

    const dim3 blk(256);

    // 1. LN1
    ln_kernel<<<MD_, blk>>>(x, ln1w, ln1b, h);

    // 2. QKV projections
    const dim3 gP(CN_ / 128, MD_ / 128);
    gemm_kernel<<<gP, blk>>>(h, wq, bq, nullptr, q, MD_, CN_, CN_, 0);
    gemm_kernel<<<gP, blk>>>(h, wk, bk, nullptr, k, MD_, CN_, CN_, 0);
    gemm_kernel<<<gP, blk>>>(h, wv, bv, nullptr, v, MD_, CN_, CN_, 0);

    // 3. Causal flash attention
    const dim3 gA(TN_ / 64, BN_ * HN_);
    attn_kernel<<<gA, blk>>>(q, k, v, ctx);

    // 4. Output projection + residual
    gemm_kernel<<<gP, blk>>>(ctx, wo, bo, x, x1, MD_, CN_, CN_, 0);

    // 5. LN2
    ln_kernel<<<MD_, blk>>>(x1, ln2w, ln2b, h2);

    // 6. FFN
    const dim3 gF1(FFD_ / 128, MD_ / 128);
    gemm_kernel<<<gF1, blk>>>(h2, w1, b1, nullptr, ff, MD_, FFD_, CN_, 1);
    gemm_kernel<<<gP,  blk>>>(ff, w2, b2, x1, out, MD_, CN_, FFD_, 0);
}

// round 3
// speedup vs baseline: 1.5937x; 1.5937x over previous
#include <cuda_runtime.h>
#include <math.h>
#include <stdint.h>

// Problem constants
#define BN_ 8
#define TN_ 1024
#define CN_ 1024
#define HN_ 16
#define DH_ 64
#define MD_ (BN_ * TN_)      // 8192 rows
#define FFD_ (4 * CN_)       // 4096

// ---------------------------------------------------------------------------
// Scratch (device globals — no allocation allowed)
// ---------------------------------------------------------------------------
__device__ float g_h  [MD_ * CN_];
__device__ float g_q  [MD_ * CN_];
__device__ float g_k  [MD_ * CN_];
__device__ float g_v  [MD_ * CN_];
__device__ float g_ctx[MD_ * CN_];
__device__ float g_x1 [MD_ * CN_];
__device__ float g_h2 [MD_ * CN_];
__device__ float g_ff [MD_ * FFD_];

// ---------------------------------------------------------------------------
// Helpers
// ---------------------------------------------------------------------------
__device__ __forceinline__ uint32_t smem_u32(const void* p) {
    uint32_t a;
    asm("{ .reg .u64 t; cvta.to.shared.u64 t, %1; cvt.u32.u64 %0, t; }" : "=r"(a) : "l"(p));
    return a;
}

__device__ __forceinline__ void cp_async16(uint32_t dst, const void* src) {
    asm volatile("cp.async.cg.shared.global [%0], [%1], 16;" :: "r"(dst), "l"(src));
}
__device__ __forceinline__ void cp_commit() {
    asm volatile("cp.async.commit_group;" ::: "memory");
}
__device__ __forceinline__ void cp_wait0() {
    asm volatile("cp.async.wait_group 0;" ::: "memory");
}

__device__ __forceinline__ uint32_t f2tf(float x) {
    uint32_t o;
    asm("cvt.rna.tf32.f32 %0, %1;" : "=r"(o) : "f"(x));
    return o;
}

__device__ __forceinline__ void mma_tf32(float* d, const uint32_t* a,
                                         uint32_t b0, uint32_t b1)
{
    asm volatile(
        "mma.sync.aligned.m16n8k8.row.col.f32.tf32.tf32.f32 "
        "{%0,%1,%2,%3}, {%4,%5,%6,%7}, {%8,%9}, {%0,%1,%2,%3};"
        : "+f"(d[0]), "+f"(d[1]), "+f"(d[2]), "+f"(d[3])
        : "r"(a[0]), "r"(a[1]), "r"(a[2]), "r"(a[3]), "r"(b0), "r"(b1));
}

__device__ __forceinline__ float gelu_exact(float x)
{
    return 0.5f * x * (1.0f + erff(x * 0.70710678118654752f));
}

// ---------------------------------------------------------------------------
// TF32 tensor-core GEMM: C[M,N] = A[M,K] @ W[K,N] + bias (+gelu) (+res)
// 128x128 CTA tile, BK=32, 256 threads (8 warps, 4x2, warp tile 32x64).
// Double-buffered smem. A via cp.async ([m][k], stride 36).
// B via LDG + 4x4 register transpose + tf32 convert ([n][k], stride 36).
// ---------------------------------------------------------------------------
#define SA_ELEMS (128 * 36)
#define SMEM_GEMM_BYTES (4 * SA_ELEMS * 4)   // 2 A bufs + 2 B bufs = 73728 B

__global__ __launch_bounds__(256, 2)
void gemm_mma(const float* __restrict__ A, const float* __restrict__ W,
              const float* __restrict__ bias, const float* __restrict__ res,
              float* __restrict__ C, int M, int N, int K, int act)
{
    extern __shared__ float sm[];
    float* smA[2] = { sm,                sm + SA_ELEMS };
    float* smB[2] = { sm + 2 * SA_ELEMS, sm + 3 * SA_ELEMS };
    const uint32_t smA_u[2] = { smem_u32(smA[0]), smem_u32(smA[1]) };

    const int tid  = threadIdx.x;
    const int wid  = tid >> 5;
    const int lane = tid & 31;
    const int g    = lane >> 2;     // groupID
    const int tq   = lane & 3;      // thread-in-group
    const int bm = blockIdx.y * 128;
    const int bn = blockIdx.x * 128;
    const int wm = (wid & 3) * 32;
    const int wn = (wid >> 2) * 64;

    // A cp.async indexing: idx = tid + 256*it -> row=idx>>3 (0..127), c4=idx&7
    // B LDG indexing: kb = tid&7 (4 k-rows), nb = tid>>3 (4 n-cols)
    const int kb = tid & 7;
    const int nb = tid >> 3;
    const float* Wb0 = W + (size_t)(4 * kb) * N + bn + 4 * nb;

    float acc[2][8][4];
    #pragma unroll
    for (int ms = 0; ms < 2; ms++)
        #pragma unroll
        for (int ns = 0; ns < 8; ns++)
            #pragma unroll
            for (int i = 0; i < 4; i++) acc[ms][ns][i] = 0.f;

    const int nChunks = K >> 5;

    // ---- A async load for chunk c into buffer b ----
    auto loadA = [&](int c, int b) {
        const float* Ab = A + (size_t)bm * K + (c << 5);
        #pragma unroll
        for (int it = 0; it < 4; ++it) {
            const int idx = tid + it * 256;
            const int row = idx >> 3;
            const int c4  = idx & 7;
            cp_async16(smA_u[b] + (uint32_t)(row * 36 + c4 * 4) * 4u,
                       Ab + (size_t)row * K + c4 * 4);
        }
    };
    // ---- B global load (regs) for chunk c ----
    float4 br[4];
    auto loadB_g = [&](int c) {
        const float* Wb = Wb0 + (size_t)(c << 5) * N;
        br[0] = *(const float4*)(Wb);
        br[1] = *(const float4*)(Wb + N);
        br[2] = *(const float4*)(Wb + 2 * (size_t)N);
        br[3] = *(const float4*)(Wb + 3 * (size_t)N);
    };
    // ---- B transpose + tf32 convert + STS into buffer b ----
    auto storeB = [&](int b) {
        float* sB = smB[b];
        float4 s0 = make_float4(br[0].x, br[1].x, br[2].x, br[3].x);
        float4 s1 = make_float4(br[0].y, br[1].y, br[2].y, br[3].y);
        float4 s2 = make_float4(br[0].z, br[1].z, br[2].z, br[3].z);
        float4 s3 = make_float4(br[0].w, br[1].w, br[2].w, br[3].w);
        #pragma unroll
        for (int i = 0; i < 4; i++) {
            float4 v = (i == 0) ? s0 : (i == 1) ? s1 : (i == 2) ? s2 : s3;
            v.x = __uint_as_float(f2tf(v.x));
            v.y = __uint_as_float(f2tf(v.y));
            v.z = __uint_as_float(f2tf(v.z));
            v.w = __uint_as_float(f2tf(v.w));
            *(float4*)(sB + (4 * nb + i) * 36 + 4 * kb) = v;
        }
    };
    // ---- compute on buffer b ----
    auto compute = [&](int b) {
        const float* sA = smA[b];
        const float* sB = smB[b];
        #pragma unroll
        for (int kk = 0; kk < 4; kk++) {
            const int c0 = kk * 8 + tq;
            const int c1 = c0 + 4;
            uint32_t a[2][4];
            #pragma unroll
            for (int ms = 0; ms < 2; ms++) {
                const int r0 = wm + ms * 16 + g;
                a[ms][0] = f2tf(sA[r0 * 36 + c0]);
                a[ms][1] = f2tf(sA[(r0 + 8) * 36 + c0]);
                a[ms][2] = f2tf(sA[r0 * 36 + c1]);
                a[ms][3] = f2tf(sA[(r0 + 8) * 36 + c1]);
            }
            #pragma unroll
            for (int ns = 0; ns < 8; ns++) {
                const int n = wn + ns * 8 + g;
                const uint32_t b0 = __float_as_uint(sB[n * 36 + c0]);
                const uint32_t b1 = __float_as_uint(sB[n * 36 + c1]);
                mma_tf32(acc[0][ns], a[0], b0, b1);
                mma_tf32(acc[1][ns], a[1], b0, b1);
            }
        }
    };

    // Prologue: chunk 0
    loadA(0, 0); cp_commit();
    loadB_g(0);
    cp_wait0();
    storeB(0);
    __syncthreads();

    for (int c = 0; c < nChunks; ++c) {
        const int cur = c & 1;
        const int nxt = cur ^ 1;
        const bool has_next = (c + 1) < nChunks;
        if (has_next) {
            loadA(c + 1, nxt); cp_commit();
            loadB_g(c + 1);
        }
        compute(cur);
        if (has_next) {
            storeB(nxt);
            cp_wait0();
            __syncthreads();
        }
    }

    // Epilogue: d[ms][ns] rows bm+wm+16ms+g(+8), cols bn+wn+8ns+2tq(+1)
    #pragma unroll
    for (int ms = 0; ms < 2; ms++) {
        const int r0 = bm + wm + 16 * ms + g;
        const int r1 = r0 + 8;
        #pragma unroll
        for (int ns = 0; ns < 8; ns++) {
            const int col = bn + wn + 8 * ns + 2 * tq;
            const float2 bb = *(const float2*)(bias + col);
            float2 o0, o1;
            o0.x = acc[ms][ns][0] + bb.x;
            o0.y = acc[ms][ns][1] + bb.y;
            o1.x = acc[ms][ns][2] + bb.x;
            o1.y = acc[ms][ns][3] + bb.y;
            if (act) {
                o0.x = gelu_exact(o0.x); o0.y = gelu_exact(o0.y);
                o1.x = gelu_exact(o1.x); o1.y = gelu_exact(o1.y);
            }
            if (res) {
                const float2 q0 = *(const float2*)(res + (size_t)r0 * N + col);
                const float2 q1 = *(const float2*)(res + (size_t)r1 * N + col);
                o0.x += q0.x; o0.y += q0.y;
                o1.x += q1.x; o1.y += q1.y;
            }
            *(float2*)(C + (size_t)r0 * N + col) = o0;
            *(float2*)(C + (size_t)r1 * N + col) = o1;
        }
    }
}

// ---------------------------------------------------------------------------
// LayerNorm: one block per row of 1024, 256 threads, one float4 per thread
// ---------------------------------------------------------------------------
__global__ __launch_bounds__(256)
void ln_kernel(const float* __restrict__ x, const float* __restrict__ w,
               const float* __restrict__ b, float* __restrict__ out)
{
    const int row = blockIdx.x;
    const int tid = threadIdx.x;
    const float4 v = *(const float4*)(x + (size_t)row * CN_ + tid * 4);

    float s  = v.x + v.y + v.z + v.w;
    float ss = v.x * v.x + v.y * v.y + v.z * v.z + v.w * v.w;
    #pragma unroll
    for (int o = 16; o > 0; o >>= 1) {
        s  += __shfl_xor_sync(0xFFFFFFFFu, s,  o);
        ss += __shfl_xor_sync(0xFFFFFFFFu, ss, o);
    }
    __shared__ float rs[8], rss[8];
    const int wid = tid >> 5, lane = tid & 31;
    if (lane == 0) { rs[wid] = s; rss[wid] = ss; }
    __syncthreads();
    float tot = 0.f, tots = 0.f;
    #pragma unroll
    for (int i = 0; i < 8; i++) { tot += rs[i]; tots += rss[i]; }

    const float mu   = tot * (1.0f / (float)CN_);
    const float var  = tots * (1.0f / (float)CN_) - mu * mu;
    const float rsig = rsqrtf(var + 1e-5f);

    const float4 wv = *(const float4*)(w + tid * 4);
    const float4 bv = *(const float4*)(b + tid * 4);
    float4 o;
    o.x = (v.x - mu) * rsig * wv.x + bv.x;
    o.y = (v.y - mu) * rsig * wv.y + bv.y;
    o.z = (v.z - mu) * rsig * wv.z + bv.z;
    o.w = (v.w - mu) * rsig * wv.w + bv.w;
    *(float4*)(out + (size_t)row * CN_ + tid * 4) = o;
}

// ---------------------------------------------------------------------------
// Flash attention (causal), fp32 SIMT (unchanged)
// ---------------------------------------------------------------------------
__global__ __launch_bounds__(256)
void attn_kernel(const float* __restrict__ q, const float* __restrict__ k,
                 const float* __restrict__ v, float* __restrict__ out)
{
    __shared__ float sQ [64][64];
    __shared__ float sKV[64][64];
    __shared__ float sP [64][64];

    const int qt  = blockIdx.x;
    const int bh  = blockIdx.y;
    const int b   = bh >> 4;
    const int h   = bh & 15;
    const int tid = threadIdx.x;
    const int r    = tid >> 2;
    const int quad = tid & 3;
    const int j0   = quad * 16;

    const size_t headoff = (size_t)h * DH_;
    const float* qbase = q + ((size_t)b * TN_ + qt * 64) * CN_ + headoff;

    #pragma unroll
    for (int it = 0; it < 4; it++) {
        const int idx = tid + it * 256;
        const int row = idx >> 4;
        const int c4  = (idx & 15) * 4;
        const float4 val = *(const float4*)(qbase + (size_t)row * CN_ + c4);
        sQ[c4 + 0][row] = val.x;
        sQ[c4 + 1][row] = val.y;
        sQ[c4 + 2][row] = val.z;
        sQ[c4 + 3][row] = val.w;
    }

    float m = -1e30f, l = 0.f;
    float o[16];
    #pragma unroll
    for (int i = 0; i < 16; i++) o[i] = 0.f;

    const float scale = 0.125f;

    for (int kt = 0; kt <= qt; kt++) {
        const float* kbase = k + ((size_t)b * TN_ + kt * 64) * CN_ + headoff;
        const float* vbase = v + ((size_t)b * TN_ + kt * 64) * CN_ + headoff;

        __syncthreads();
        #pragma unroll
        for (int it = 0; it < 4; it++) {
            const int idx = tid + it * 256;
            const int row = idx >> 4;
            const int c4  = (idx & 15) * 4;
            const float4 val = *(const float4*)(kbase + (size_t)row * CN_ + c4);
            sKV[c4 + 0][row] = val.x;
            sKV[c4 + 1][row] = val.y;
            sKV[c4 + 2][row] = val.z;
            sKV[c4 + 3][row] = val.w;
        }
        __syncthreads();

        float s[16];
        #pragma unroll
        for (int i = 0; i < 16; i++) s[i] = 0.f;
        #pragma unroll 16
        for (int kk = 0; kk < 64; kk++) {
            const float qv = sQ[kk][r];
            const float4* kp = (const float4*)&sKV[kk][j0];
            const float4 k0v = kp[0], k1v = kp[1], k2v = kp[2], k3v = kp[3];
            s[0]  += qv * k0v.x; s[1]  += qv * k0v.y; s[2]  += qv * k0v.z; s[3]  += qv * k0v.w;
            s[4]  += qv * k1v.x; s[5]  += qv * k1v.y; s[6]  += qv * k1v.z; s[7]  += qv * k1v.w;
            s[8]  += qv * k2v.x; s[9]  += qv * k2v.y; s[10] += qv * k2v.z; s[11] += qv * k2v.w;
            s[12] += qv * k3v.x; s[13] += qv * k3v.y; s[14] += qv * k3v.z; s[15] += qv * k3v.w;
        }

        float tmax = -1e30f;
        const bool diag = (kt == qt);
        #pragma unroll
        for (int i = 0; i < 16; i++) {
            s[i] *= scale;
            if (diag && (j0 + i) > r) s[i] = -1e30f;
            tmax = fmaxf(tmax, s[i]);
        }
        tmax = fmaxf(tmax, __shfl_xor_sync(0xFFFFFFFFu, tmax, 1));
        tmax = fmaxf(tmax, __shfl_xor_sync(0xFFFFFFFFu, tmax, 2));

        const float mnew  = fmaxf(m, tmax);
        const float alpha = __expf(m - mnew);
        float psum = 0.f;
        float p[16];
        #pragma unroll
        for (int i = 0; i < 16; i++) {
            p[i] = __expf(s[i] - mnew);
            psum += p[i];
        }
        psum += __shfl_xor_sync(0xFFFFFFFFu, psum, 1);
        psum += __shfl_xor_sync(0xFFFFFFFFu, psum, 2);
        l = l * alpha + psum;
        m = mnew;
        #pragma unroll
        for (int i = 0; i < 16; i++) o[i] *= alpha;

        #pragma unroll
        for (int i = 0; i < 16; i++) sP[j0 + i][r] = p[i];
        __syncthreads();

        #pragma unroll
        for (int it = 0; it < 4; it++) {
            const int idx = tid + it * 256;
            const int row = idx >> 4;
            const int c4  = (idx & 15) * 4;
            const float4 val = *(const float4*)(vbase + (size_t)row * CN_ + c4);
            *(float4*)&sKV[row][c4] = val;
        }
        __syncthreads();

        #pragma unroll 16
        for (int c = 0; c < 64; c++) {
            const float pv = sP[c][r];
            const float4* vp = (const float4*)&sKV[c][j0];
            const float4 v0 = vp[0], v1 = vp[1], v2 = vp[2], v3 = vp[3];
            o[0]  += pv * v0.x; o[1]  += pv * v0.y; o[2]  += pv * v0.z; o[3]  += pv * v0.w;
            o[4]  += pv * v1.x; o[5]  += pv * v1.y; o[6]  += pv * v1.z; o[7]  += pv * v1.w;
            o[8]  += pv * v2.x; o[9]  += pv * v2.y; o[10] += pv * v2.z; o[11] += pv * v2.w;
            o[12] += pv * v3.x; o[13] += pv * v3.y; o[14] += pv * v3.z; o[15] += pv * v3.w;
        }
    }

    const float inv = 1.0f / l;
    float* obase = out + ((size_t)b * TN_ + qt * 64 + r) * CN_ + headoff + j0;
    #pragma unroll
    for (int jv = 0; jv < 4; jv++) {
        float4 ov;
        ov.x = o[jv * 4 + 0] * inv;
        ov.y = o[jv * 4 + 1] * inv;
        ov.z = o[jv * 4 + 2] * inv;
        ov.w = o[jv * 4 + 3] * inv;
        *(float4*)(obase + jv * 4) = ov;
    }
}

// ---------------------------------------------------------------------------
// Launch
// ---------------------------------------------------------------------------
extern "C" void kernel_launch(void* const* d_in, const int* in_sizes, int n_in,
                              void* d_out, int out_size)
{
    const float* x    = (const float*)d_in[0];
    const float* ln1w = (const float*)d_in[2];
    const float* ln1b = (const float*)d_in[3];
    const float* ln2w = (const float*)d_in[4];
    const float* ln2b = (const float*)d_in[5];
    const float* wq   = (const float*)d_in[6];
    const float* bq   = (const float*)d_in[7];
    const float* wk   = (const float*)d_in[8];
    const float* bk   = (const float*)d_in[9];
    const float* wv   = (const float*)d_in[10];
    const float* bv   = (const float*)d_in[11];
    const float* wo   = (const float*)d_in[12];
    const float* bo   = (const float*)d_in[13];
    const float* w1   = (const float*)d_in[14];
    const float* b1   = (const float*)d_in[15];
    const float* w2   = (const float*)d_in[16];
    const float* b2   = (const float*)d_in[17];
    float* out = (float*)d_out;

    float *h, *q, *k, *v, *ctx, *x1, *h2, *ff;
    cudaGetSymbolAddress((void**)&h,   g_h);
    cudaGetSymbolAddress((void**)&q,   g_q);
    cudaGetSymbolAddress((void**)&k,   g_k);
    cudaGetSymbolAddress((void**)&v,   g_v);
    cudaGetSymbolAddress((void**)&ctx, g_ctx);
    cudaGetSymbolAddress((void**)&x1,  g_x1);
    cudaGetSymbolAddress((void**)&h2,  g_h2);
    cudaGetSymbolAddress((void**)&ff,  g_ff);

    cudaFuncSetAttribute(gemm_mma, cudaFuncAttributeMaxDynamicSharedMemorySize,
                         SMEM_GEMM_BYTES);

    const dim3 blk(256);

    // 1. LN1
    ln_kernel<<<MD_, blk>>>(x, ln1w, ln1b, h);

    // 2. QKV projections (tf32 mma.sync)
    const dim3 gP(CN_ / 128, MD_ / 128);
    gemm_mma<<<gP, blk, SMEM_GEMM_BYTES>>>(h, wq, bq, nullptr, q, MD_, CN_, CN_, 0);
    gemm_mma<<<gP, blk, SMEM_GEMM_BYTES>>>(h, wk, bk, nullptr, k, MD_, CN_, CN_, 0);
    gemm_mma<<<gP, blk, SMEM_GEMM_BYTES>>>(h, wv, bv, nullptr, v, MD_, CN_, CN_, 0);

    // 3. Causal flash attention
    const dim3 gA(TN_ / 64, BN_ * HN_);
    attn_kernel<<<gA, blk>>>(q, k, v, ctx);

    // 4. Output projection + residual
    gemm_mma<<<gP, blk, SMEM_GEMM_BYTES>>>(ctx, wo, bo, x, x1, MD_, CN_, CN_, 0);

    // 5. LN2
    ln_kernel<<<MD_, blk>>>(x1, ln2w, ln2b, h2);

    // 6. FFN
    const dim3 gF1(FFD_ / 128, MD_ / 128);
    gemm_mma<<<gF1, blk, SMEM_GEMM_BYTES>>>(h2, w1, b1, nullptr, ff, MD_, FFD_, CN_, 1);
    gemm_mma<<<gP,  blk, SMEM_GEMM_BYTES>>>(ff, w2, b2, x1, out, MD_, CN_, FFD_, 0);
}

// round 5
// speedup vs baseline: 4.3662x; 2.7396x over previous
#include <cuda_runtime.h>
#include <math.h>
#include <stdint.h>

// Problem constants
#define BN_ 8
#define TN_ 1024
#define CN_ 1024
#define HN_ 16
#define DH_ 64
#define MD_ (BN_ * TN_)      // 8192 rows
#define FFD_ (4 * CN_)       // 4096

// ---------------------------------------------------------------------------
// Scratch (device globals — no allocation allowed)
// ---------------------------------------------------------------------------
__device__ float g_h  [MD_ * CN_];
__device__ float g_q  [MD_ * CN_];
__device__ float g_k  [MD_ * CN_];
__device__ float g_v  [MD_ * CN_];
__device__ float g_ctx[MD_ * CN_];
__device__ float g_x1 [MD_ * CN_];
__device__ float g_h2 [MD_ * CN_];
__device__ float g_ff [MD_ * FFD_];
// tf32-rounded weight copies
__device__ float g_wqr[CN_ * CN_];
__device__ float g_wkr[CN_ * CN_];
__device__ float g_wvr[CN_ * CN_];
__device__ float g_wor[CN_ * CN_];
__device__ float g_w1r[CN_ * FFD_];
__device__ float g_w2r[FFD_ * CN_];

// ---------------------------------------------------------------------------
// Helpers
// ---------------------------------------------------------------------------
__device__ __forceinline__ uint32_t smem_u32(const void* p) {
    uint32_t a;
    asm("{ .reg .u64 t; cvta.to.shared.u64 t, %1; cvt.u32.u64 %0, t; }" : "=r"(a) : "l"(p));
    return a;
}
__device__ __forceinline__ void cp_async16(uint32_t dst, const void* src) {
    asm volatile("cp.async.cg.shared.global [%0], [%1], 16;" :: "r"(dst), "l"(src));
}
__device__ __forceinline__ void cp_commit() {
    asm volatile("cp.async.commit_group;" ::: "memory");
}
__device__ __forceinline__ void cp_wait0() {
    asm volatile("cp.async.wait_group 0;" ::: "memory");
}
__device__ __forceinline__ void cp_wait1() {
    asm volatile("cp.async.wait_group 1;" ::: "memory");
}
__device__ __forceinline__ uint32_t f2tf(float x) {
    uint32_t o;
    asm("cvt.rna.tf32.f32 %0, %1;" : "=r"(o) : "f"(x));
    return o;
}
__device__ __forceinline__ float f2tf_f(float x) { return __uint_as_float(f2tf(x)); }

__device__ __forceinline__ void mma_tf32(float* d, const uint32_t* a,
                                         uint32_t b0, uint32_t b1)
{
    asm volatile(
        "mma.sync.aligned.m16n8k8.row.col.f32.tf32.tf32.f32 "
        "{%0,%1,%2,%3}, {%4,%5,%6,%7}, {%8,%9}, {%0,%1,%2,%3};"
        : "+f"(d[0]), "+f"(d[1]), "+f"(d[2]), "+f"(d[3])
        : "r"(a[0]), "r"(a[1]), "r"(a[2]), "r"(a[3]), "r"(b0), "r"(b1));
}

__device__ __forceinline__ float gelu_exact(float x)
{
    return 0.5f * x * (1.0f + erff(x * 0.70710678118654752f));
}

// ---------------------------------------------------------------------------
// Weight pre-rounding to tf32 (runs every launch; ~15us total)
// ---------------------------------------------------------------------------
__global__ __launch_bounds__(256)
void round_w(const float* __restrict__ src, float* __restrict__ dst, int n4)
{
    const int i = blockIdx.x * 256 + threadIdx.x;
    if (i < n4) {
        float4 v = ((const float4*)src)[i];
        v.x = f2tf_f(v.x); v.y = f2tf_f(v.y);
        v.z = f2tf_f(v.z); v.w = f2tf_f(v.w);
        ((float4*)dst)[i] = v;
    }
}

// ---------------------------------------------------------------------------
// TF32 tensor-core GEMM: C[M,N] = A[M,K] @ W[K,N] + bias (+gelu) (+res)
// 128x128 CTA tile, BK=32, 256 threads (8 warps 4x2, warp tile 32x64).
// 3-stage cp.async pipeline; A [m][k] stride 36, B [k][n] stride 136
// (128 data + 8 pad -> B-frag LDS bank = (8*tq+g)%32, conflict-free).
// gridDim.z selects among up to 3 (W,bias,out) triples (merged QKV).
// ---------------------------------------------------------------------------
#define SA_STR 36
#define SB_STR 136
#define SA_W (128 * SA_STR)          // 4608 words
#define SB_W (32 * SB_STR)           // 4352 words
#define SMEM_GEMM_BYTES (3 * (SA_W + SB_W) * 4)   // 107520 B

__global__ __launch_bounds__(256, 2)
void gemm_mma(const float* __restrict__ A,
              const float* W0, const float* W1, const float* W2,
              const float* b0p, const float* b1p, const float* b2p,
              float* o0p, float* o1p, float* o2p,
              const float* __restrict__ res,
              int M, int N, int K, int act, int rnd)
{
    const int z = blockIdx.z;
    const float* W    = (z == 0) ? W0  : (z == 1) ? W1  : W2;
    const float* bias = (z == 0) ? b0p : (z == 1) ? b1p : b2p;
    float*       C    = (z == 0) ? o0p : (z == 1) ? o1p : o2p;

    extern __shared__ float sm[];
    float* smA[3] = { sm, sm + (SA_W + SB_W), sm + 2 * (SA_W + SB_W) };
    float* smB[3] = { smA[0] + SA_W, smA[1] + SA_W, smA[2] + SA_W };
    const uint32_t smA_u[3] = { smem_u32(smA[0]), smem_u32(smA[1]), smem_u32(smA[2]) };
    const uint32_t smB_u[3] = { smem_u32(smB[0]), smem_u32(smB[1]), smem_u32(smB[2]) };

    const int tid  = threadIdx.x;
    const int wid  = tid >> 5;
    const int lane = tid & 31;
    const int g    = lane >> 2;
    const int tq   = lane & 3;
    const int bm = blockIdx.y * 128;
    const int bn = blockIdx.x * 128;
    const int wm = (wid & 3) * 32;
    const int wn = (wid >> 2) * 64;

    float acc[2][8][4];
    #pragma unroll
    for (int ms = 0; ms < 2; ms++)
        #pragma unroll
        for (int ns = 0; ns < 8; ns++)
            #pragma unroll
            for (int i = 0; i < 4; i++) acc[ms][ns][i] = 0.f;

    const int nChunks = K >> 5;

    auto loadAB = [&](int c, int b) {
        const float* Ab = A + (size_t)bm * K + (c << 5);
        #pragma unroll
        for (int it = 0; it < 4; ++it) {          // A: 128 rows x 8 float4
            const int idx = tid + it * 256;
            const int row = idx >> 3;
            const int c4  = idx & 7;
            cp_async16(smA_u[b] + (uint32_t)(row * SA_STR + c4 * 4) * 4u,
                       Ab + (size_t)row * K + c4 * 4);
        }
        const float* Wb = W + (size_t)(c << 5) * N + bn;
        #pragma unroll
        for (int it = 0; it < 4; ++it) {          // B: 32 k-rows x 32 float4
            const int idx = tid + it * 256;
            const int k   = idx >> 5;
            const int n4  = (idx & 31) * 4;
            cp_async16(smB_u[b] + (uint32_t)(k * SB_STR + n4) * 4u,
                       Wb + (size_t)k * N + n4);
        }
    };

    auto compute = [&](int b) {
        const float* sA = smA[b];
        const float* sB = smB[b];
        #pragma unroll
        for (int kk = 0; kk < 4; kk++) {
            const int c0 = kk * 8 + tq;
            const int c1 = c0 + 4;
            uint32_t a[2][4];
            #pragma unroll
            for (int ms = 0; ms < 2; ms++) {
                const int r0 = wm + ms * 16 + g;
                a[ms][0] = __float_as_uint(sA[r0 * SA_STR + c0]);
                a[ms][1] = __float_as_uint(sA[(r0 + 8) * SA_STR + c0]);
                a[ms][2] = __float_as_uint(sA[r0 * SA_STR + c1]);
                a[ms][3] = __float_as_uint(sA[(r0 + 8) * SA_STR + c1]);
            }
            #pragma unroll
            for (int ns = 0; ns < 8; ns++) {
                const int n = wn + ns * 8 + g;
                const uint32_t b0 = __float_as_uint(sB[c0 * SB_STR + n]);
                const uint32_t b1 = __float_as_uint(sB[c1 * SB_STR + n]);
                mma_tf32(acc[0][ns], a[0], b0, b1);
                mma_tf32(acc[1][ns], a[1], b0, b1);
            }
        }
    };

    // 3-stage pipeline, 1 sync per chunk
    loadAB(0, 0); cp_commit();
    if (nChunks > 1) { loadAB(1, 1); cp_commit(); }

    for (int c = 0; c < nChunks; ++c) {
        if (c + 1 < nChunks) cp_wait1(); else cp_wait0();
        __syncthreads();
        compute(c % 3);
        if (c + 2 < nChunks) { loadAB(c + 2, (c + 2) % 3); cp_commit(); }
    }

    // Epilogue
    #pragma unroll
    for (int ms = 0; ms < 2; ms++) {
        const int r0 = bm + wm + 16 * ms + g;
        const int r1 = r0 + 8;
        #pragma unroll
        for (int ns = 0; ns < 8; ns++) {
            const int col = bn + wn + 8 * ns + 2 * tq;
            const float2 bb = *(const float2*)(bias + col);
            float2 o0, o1;
            o0.x = acc[ms][ns][0] + bb.x;
            o0.y = acc[ms][ns][1] + bb.y;
            o1.x = acc[ms][ns][2] + bb.x;
            o1.y = acc[ms][ns][3] + bb.y;
            if (act) {
                o0.x = gelu_exact(o0.x); o0.y = gelu_exact(o0.y);
                o1.x = gelu_exact(o1.x); o1.y = gelu_exact(o1.y);
            }
            if (res) {
                const float2 q0 = *(const float2*)(res + (size_t)r0 * N + col);
                const float2 q1 = *(const float2*)(res + (size_t)r1 * N + col);
                o0.x += q0.x; o0.y += q0.y;
                o1.x += q1.x; o1.y += q1.y;
            }
            if (rnd) {
                o0.x = f2tf_f(o0.x); o0.y = f2tf_f(o0.y);
                o1.x = f2tf_f(o1.x); o1.y = f2tf_f(o1.y);
            }
            *(float2*)(C + (size_t)r0 * N + col) = o0;
            *(float2*)(C + (size_t)r1 * N + col) = o1;
        }
    }
}

// ---------------------------------------------------------------------------
// LayerNorm: one block per row, 256 threads; optional tf32 rounding of output
// ---------------------------------------------------------------------------
__global__ __launch_bounds__(256)
void ln_kernel(const float* __restrict__ x, const float* __restrict__ w,
               const float* __restrict__ b, float* __restrict__ out, int rnd)
{
    const int row = blockIdx.x;
    const int tid = threadIdx.x;
    const float4 v = *(const float4*)(x + (size_t)row * CN_ + tid * 4);

    float s  = v.x + v.y + v.z + v.w;
    float ss = v.x * v.x + v.y * v.y + v.z * v.z + v.w * v.w;
    #pragma unroll
    for (int o = 16; o > 0; o >>= 1) {
        s  += __shfl_xor_sync(0xFFFFFFFFu, s,  o);
        ss += __shfl_xor_sync(0xFFFFFFFFu, ss, o);
    }
    __shared__ float rs[8], rss[8];
    const int wid = tid >> 5, lane = tid & 31;
    if (lane == 0) { rs[wid] = s; rss[wid] = ss; }
    __syncthreads();
    float tot = 0.f, tots = 0.f;
    #pragma unroll
    for (int i = 0; i < 8; i++) { tot += rs[i]; tots += rss[i]; }

    const float mu   = tot * (1.0f / (float)CN_);
    const float var  = tots * (1.0f / (float)CN_) - mu * mu;
    const float rsig = rsqrtf(var + 1e-5f);

    const float4 wv = *(const float4*)(w + tid * 4);
    const float4 bv = *(const float4*)(b + tid * 4);
    float4 o;
    o.x = (v.x - mu) * rsig * wv.x + bv.x;
    o.y = (v.y - mu) * rsig * wv.y + bv.y;
    o.z = (v.z - mu) * rsig * wv.z + bv.z;
    o.w = (v.w - mu) * rsig * wv.w + bv.w;
    if (rnd) {
        o.x = f2tf_f(o.x); o.y = f2tf_f(o.y);
        o.z = f2tf_f(o.z); o.w = f2tf_f(o.w);
    }
    *(float4*)(out + (size_t)row * CN_ + tid * 4) = o;
}

// ---------------------------------------------------------------------------
// Tensor-core flash attention (causal, tf32 mma).
// Block: 128 threads (4 warps); tile 64 (rows) x 64 (kv) x d=64.
// Warp w owns rows 16w..16w+15. Q frags register-resident (scale folded in).
// smem: sQP (Q then reused for P, stride 68), double-buffered K (stride 68)
// and V (stride 72). cp.async loads.
// ---------------------------------------------------------------------------
#define AQ_STR 68
#define AK_STR 68
#define AV_STR 72
#define QP_W  (64 * AQ_STR)     // 4352
#define K_W   (64 * AK_STR)     // 4352
#define V_W   (64 * AV_STR)     // 4608
#define SMEM_ATTN_BYTES ((QP_W + 2 * (K_W + V_W)) * 4)   // 89088 B

__global__ __launch_bounds__(128)
void attn_tc(const float* __restrict__ q, const float* __restrict__ k,
             const float* __restrict__ v, float* __restrict__ out)
{
    extern __shared__ float sm[];
    float* sQP   = sm;
    float* sK[2] = { sm + QP_W,            sm + QP_W + K_W + V_W };
    float* sV[2] = { sm + QP_W + K_W,      sm + QP_W + 2 * K_W + V_W };
    const uint32_t sQP_u  = smem_u32(sQP);
    const uint32_t sK_u[2] = { smem_u32(sK[0]), smem_u32(sK[1]) };
    const uint32_t sV_u[2] = { smem_u32(sV[0]), smem_u32(sV[1]) };

    const int qt  = blockIdx.x;
    const int bh  = blockIdx.y;
    const int b   = bh >> 4;
    const int h   = bh & 15;
    const int tid  = threadIdx.x;
    const int wid  = tid >> 5;
    const int lane = tid & 31;
    const int g    = lane >> 2;
    const int tq   = lane & 3;

    const size_t headoff = (size_t)h * DH_;
    const float* qbase = q + ((size_t)b * TN_ + qt * 64) * CN_ + headoff;

    // Q tile -> smem (cp.async), grouped with KV(0)
    #pragma unroll
    for (int it = 0; it < 8; ++it) {
        const int idx = tid + it * 128;
        const int row = idx >> 4;
        const int d4  = (idx & 15) * 4;
        cp_async16(sQP_u + (uint32_t)(row * AQ_STR + d4) * 4u,
                   qbase + (size_t)row * CN_ + d4);
    }
    auto loadKV = [&](int kt, int bb) {
        const float* kb = k + ((size_t)b * TN_ + kt * 64) * CN_ + headoff;
        const float* vb = v + ((size_t)b * TN_ + kt * 64) * CN_ + headoff;
        #pragma unroll
        for (int it = 0; it < 8; ++it) {
            const int idx = tid + it * 128;
            const int row = idx >> 4;
            const int d4  = (idx & 15) * 4;
            cp_async16(sK_u[bb] + (uint32_t)(row * AK_STR + d4) * 4u,
                       kb + (size_t)row * CN_ + d4);
        }
        #pragma unroll
        for (int it = 0; it < 8; ++it) {
            const int idx = tid + it * 128;
            const int row = idx >> 4;
            const int d4  = (idx & 15) * 4;
            cp_async16(sV_u[bb] + (uint32_t)(row * AV_STR + d4) * 4u,
                       vb + (size_t)row * CN_ + d4);
        }
    };

    loadKV(0, 0);
    cp_commit();
    cp_wait0();
    __syncthreads();

    // Extract Q fragments (fold 1/sqrt(64)=0.125 into Q; exact power of 2)
    uint32_t qa[8][4];
    {
        const int r0 = 16 * wid + g;
        #pragma unroll
        for (int kk = 0; kk < 8; kk++) {
            const int c0 = kk * 8 + tq;
            qa[kk][0] = __float_as_uint(0.125f * sQP[r0 * AQ_STR + c0]);
            qa[kk][1] = __float_as_uint(0.125f * sQP[(r0 + 8) * AQ_STR + c0]);
            qa[kk][2] = __float_as_uint(0.125f * sQP[r0 * AQ_STR + c0 + 4]);
            qa[kk][3] = __float_as_uint(0.125f * sQP[(r0 + 8) * AQ_STR + c0 + 4]);
        }
    }
    __syncthreads();   // sQP now reusable as sP

    float o[8][4];
    #pragma unroll
    for (int ns = 0; ns < 8; ns++)
        #pragma unroll
        for (int i = 0; i < 4; i++) o[ns][i] = 0.f;
    float m0 = -1e30f, m1 = -1e30f, l0 = 0.f, l1 = 0.f;

    const int r_in0 = 16 * wid + g;
    const int r_in1 = r_in0 + 8;

    for (int kt = 0; kt <= qt; kt++) {
        const int cur = kt & 1;
        if (kt + 1 <= qt) { loadKV(kt + 1, cur ^ 1); cp_commit(); }
        if (kt + 1 <= qt) cp_wait1(); else cp_wait0();
        __syncthreads();

        // ---- S = Q K^T ----
        float s[8][4];
        #pragma unroll
        for (int ns = 0; ns < 8; ns++)
            #pragma unroll
            for (int i = 0; i < 4; i++) s[ns][i] = 0.f;
        const float* sKc = sK[cur];
        #pragma unroll
        for (int kk = 0; kk < 8; kk++) {
            const int c0 = kk * 8 + tq;
            #pragma unroll
            for (int ns = 0; ns < 8; ns++) {
                const int n = 8 * ns + g;
                const uint32_t b0 = __float_as_uint(sKc[n * AK_STR + c0]);
                const uint32_t b1 = __float_as_uint(sKc[n * AK_STR + c0 + 4]);
                mma_tf32(s[ns], qa[kk], b0, b1);
            }
        }

        // ---- causal mask (diag tile only) ----
        if (kt == qt) {
            #pragma unroll
            for (int ns = 0; ns < 8; ns++) {
                const int c0 = 8 * ns + 2 * tq;
                if (c0     > r_in0) s[ns][0] = -1e30f;
                if (c0 + 1 > r_in0) s[ns][1] = -1e30f;
                if (c0     > r_in1) s[ns][2] = -1e30f;
                if (c0 + 1 > r_in1) s[ns][3] = -1e30f;
            }
        }

        // ---- online softmax ----
        float rm0 = -1e30f, rm1 = -1e30f;
        #pragma unroll
        for (int ns = 0; ns < 8; ns++) {
            rm0 = fmaxf(rm0, fmaxf(s[ns][0], s[ns][1]));
            rm1 = fmaxf(rm1, fmaxf(s[ns][2], s[ns][3]));
        }
        rm0 = fmaxf(rm0, __shfl_xor_sync(0xFFFFFFFFu, rm0, 1));
        rm0 = fmaxf(rm0, __shfl_xor_sync(0xFFFFFFFFu, rm0, 2));
        rm1 = fmaxf(rm1, __shfl_xor_sync(0xFFFFFFFFu, rm1, 1));
        rm1 = fmaxf(rm1, __shfl_xor_sync(0xFFFFFFFFu, rm1, 2));

        const float nm0 = fmaxf(m0, rm0), nm1 = fmaxf(m1, rm1);
        const float a0 = __expf(m0 - nm0), a1 = __expf(m1 - nm1);
        float ps0 = 0.f, ps1 = 0.f;
        float p[8][4];
        #pragma unroll
        for (int ns = 0; ns < 8; ns++) {
            p[ns][0] = f2tf_f(__expf(s[ns][0] - nm0));
            p[ns][1] = f2tf_f(__expf(s[ns][1] - nm0));
            p[ns][2] = f2tf_f(__expf(s[ns][2] - nm1));
            p[ns][3] = f2tf_f(__expf(s[ns][3] - nm1));
            ps0 += p[ns][0] + p[ns][1];
            ps1 += p[ns][2] + p[ns][3];
        }
        ps0 += __shfl_xor_sync(0xFFFFFFFFu, ps0, 1);
        ps0 += __shfl_xor_sync(0xFFFFFFFFu, ps0, 2);
        ps1 += __shfl_xor_sync(0xFFFFFFFFu, ps1, 1);
        ps1 += __shfl_xor_sync(0xFFFFFFFFu, ps1, 2);
        l0 = l0 * a0 + ps0;  m0 = nm0;
        l1 = l1 * a1 + ps1;  m1 = nm1;
        #pragma unroll
        for (int ns = 0; ns < 8; ns++) {
            o[ns][0] *= a0; o[ns][1] *= a0;
            o[ns][2] *= a1; o[ns][3] *= a1;
        }

        // ---- store P (reuse sQP) ----
        #pragma unroll
        for (int ns = 0; ns < 8; ns++) {
            *(float2*)(sQP + r_in0 * AQ_STR + 8 * ns + 2 * tq) = make_float2(p[ns][0], p[ns][1]);
            *(float2*)(sQP + r_in1 * AQ_STR + 8 * ns + 2 * tq) = make_float2(p[ns][2], p[ns][3]);
        }
        __syncthreads();

        // ---- O += P V ----
        const float* sVc = sV[cur];
        #pragma unroll
        for (int kk = 0; kk < 8; kk++) {
            const int c0 = kk * 8 + tq;
            uint32_t pa[4];
            pa[0] = __float_as_uint(sQP[r_in0 * AQ_STR + c0]);
            pa[1] = __float_as_uint(sQP[r_in1 * AQ_STR + c0]);
            pa[2] = __float_as_uint(sQP[r_in0 * AQ_STR + c0 + 4]);
            pa[3] = __float_as_uint(sQP[r_in1 * AQ_STR + c0 + 4]);
            #pragma unroll
            for (int ns = 0; ns < 8; ns++) {
                const int n = 8 * ns + g;
                const uint32_t b0 = __float_as_uint(sVc[c0 * AV_STR + n]);
                const uint32_t b1 = __float_as_uint(sVc[(c0 + 4) * AV_STR + n]);
                mma_tf32(o[ns], pa, b0, b1);
            }
        }
        __syncthreads();   // P reads done before next tile overwrites sQP/sK/sV
    }

    // ---- epilogue: O/l, round to tf32, store ----
    const float inv0 = 1.0f / l0;
    const float inv1 = 1.0f / l1;
    float* ob0 = out + ((size_t)b * TN_ + qt * 64 + r_in0) * CN_ + headoff;
    float* ob1 = out + ((size_t)b * TN_ + qt * 64 + r_in1) * CN_ + headoff;
    #pragma unroll
    for (int ns = 0; ns < 8; ns++) {
        const int d = 8 * ns + 2 * tq;
        *(float2*)(ob0 + d) = make_float2(f2tf_f(o[ns][0] * inv0), f2tf_f(o[ns][1] * inv0));
        *(float2*)(ob1 + d) = make_float2(f2tf_f(o[ns][2] * inv1), f2tf_f(o[ns][3] * inv1));
    }
}

// ---------------------------------------------------------------------------
// Launch
// ---------------------------------------------------------------------------
extern "C" void kernel_launch(void* const* d_in, const int* in_sizes, int n_in,
                              void* d_out, int out_size)
{
    const float* x    = (const float*)d_in[0];
    const float* ln1w = (const float*)d_in[2];
    const float* ln1b = (const float*)d_in[3];
    const float* ln2w = (const float*)d_in[4];
    const float* ln2b = (const float*)d_in[5];
    const float* wq   = (const float*)d_in[6];
    const float* bq   = (const float*)d_in[7];
    const float* wk   = (const float*)d_in[8];
    const float* bk   = (const float*)d_in[9];
    const float* wv   = (const float*)d_in[10];
    const float* bv   = (const float*)d_in[11];
    const float* wo   = (const float*)d_in[12];
    const float* bo   = (const float*)d_in[13];
    const float* w1   = (const float*)d_in[14];
    const float* b1   = (const float*)d_in[15];
    const float* w2   = (const float*)d_in[16];
    const float* b2   = (const float*)d_in[17];
    float* out = (float*)d_out;

    float *h, *q, *k, *v, *ctx, *x1, *h2, *ff;
    float *wqr, *wkr, *wvr, *wor, *w1r, *w2r;
    cudaGetSymbolAddress((void**)&h,   g_h);
    cudaGetSymbolAddress((void**)&q,   g_q);
    cudaGetSymbolAddress((void**)&k,   g_k);
    cudaGetSymbolAddress((void**)&v,   g_v);
    cudaGetSymbolAddress((void**)&ctx, g_ctx);
    cudaGetSymbolAddress((void**)&x1,  g_x1);
    cudaGetSymbolAddress((void**)&h2,  g_h2);
    cudaGetSymbolAddress((void**)&ff,  g_ff);
    cudaGetSymbolAddress((void**)&wqr, g_wqr);
    cudaGetSymbolAddress((void**)&wkr, g_wkr);
    cudaGetSymbolAddress((void**)&wvr, g_wvr);
    cudaGetSymbolAddress((void**)&wor, g_wor);
    cudaGetSymbolAddress((void**)&w1r, g_w1r);
    cudaGetSymbolAddress((void**)&w2r, g_w2r);

    cudaFuncSetAttribute(gemm_mma, cudaFuncAttributeMaxDynamicSharedMemorySize,
                         SMEM_GEMM_BYTES);
    cudaFuncSetAttribute(attn_tc, cudaFuncAttributeMaxDynamicSharedMemorySize,
                         SMEM_ATTN_BYTES);

    const dim3 blk(256);

    // 0. Round weights to tf32 (RNA) once per replay
    const int nP = CN_ * CN_ / 4, nF = CN_ * FFD_ / 4;
    round_w<<<(nP + 255) / 256, blk>>>(wq, wqr, nP);
    round_w<<<(nP + 255) / 256, blk>>>(wk, wkr, nP);
    round_w<<<(nP + 255) / 256, blk>>>(wv, wvr, nP);
    round_w<<<(nP + 255) / 256, blk>>>(wo, wor, nP);
    round_w<<<(nF + 255) / 256, blk>>>(w1, w1r, nF);
    round_w<<<(nF + 255) / 256, blk>>>(w2, w2r, nF);

    // 1. LN1 (output rounded to tf32)
    ln_kernel<<<MD_, blk>>>(x, ln1w, ln1b, h, 1);

    // 2. QKV projections merged (z=3), outputs rounded to tf32
    const dim3 gQKV(CN_ / 128, MD_ / 128, 3);
    gemm_mma<<<gQKV, blk, SMEM_GEMM_BYTES>>>(h, wqr, wkr, wvr, bq, bk, bv,
                                             q, k, v, nullptr,
                                             MD_, CN_, CN_, 0, 1);

    // 3. Causal flash attention (tensor cores), ctx rounded to tf32
    const dim3 gA(TN_ / 64, BN_ * HN_);
    attn_tc<<<gA, dim3(128), SMEM_ATTN_BYTES>>>(q, k, v, ctx);

    // 4. Output projection + residual (fp32 out)
    const dim3 gP(CN_ / 128, MD_ / 128, 1);
    gemm_mma<<<gP, blk, SMEM_GEMM_BYTES>>>(ctx, wor, wor, wor, bo, bo, bo,
                                           x1, x1, x1, x,
                                           MD_, CN_, CN_, 0, 0);

    // 5. LN2 (rounded)
    ln_kernel<<<MD_, blk>>>(x1, ln2w, ln2b, h2, 1);

    // 6. FFN
    const dim3 gF1(FFD_ / 128, MD_ / 128, 1);
    gemm_mma<<<gF1, blk, SMEM_GEMM_BYTES>>>(h2, w1r, w1r, w1r, b1, b1, b1,
                                            ff, ff, ff, nullptr,
                                            MD_, FFD_, CN_, 1, 1);
    gemm_mma<<<gP, blk, SMEM_GEMM_BYTES>>>(ff, w2r, w2r, w2r, b2, b2, b2,
                                           out, out, out, x1,
                                           MD_, CN_, FFD_, 0, 0);
}

// round 6
// speedup vs baseline: 7.3877x; 1.6920x over previous
#include <cuda_runtime.h>
#include <cuda_fp16.h>
#include <math.h>
#include <stdint.h>

// Problem constants
#define BN_ 8
#define TN_ 1024
#define CN_ 1024
#define HN_ 16
#define DH_ 64
#define MD_ (BN_ * TN_)      // 8192 rows
#define FFD_ (4 * CN_)       // 4096

// ---------------------------------------------------------------------------
// Scratch (device globals — no allocation allowed)
// ---------------------------------------------------------------------------
__device__ __half g_h  [MD_ * CN_];
__device__ __half g_q  [MD_ * CN_];
__device__ __half g_k  [MD_ * CN_];
__device__ __half g_v  [MD_ * CN_];
__device__ __half g_ctx[MD_ * CN_];
__device__ float  g_x1 [MD_ * CN_];
__device__ __half g_h2 [MD_ * CN_];
__device__ __half g_ff [MD_ * FFD_];
// transposed half weights: Wt[n][k] = W[k][n]
__device__ __half g_wqt[CN_ * CN_];
__device__ __half g_wkt[CN_ * CN_];
__device__ __half g_wvt[CN_ * CN_];
__device__ __half g_wot[CN_ * CN_];
__device__ __half g_w1t[FFD_ * CN_];
__device__ __half g_w2t[CN_ * FFD_];

// ---------------------------------------------------------------------------
// Helpers
// ---------------------------------------------------------------------------
__device__ __forceinline__ uint32_t smem_u32(const void* p) {
    uint32_t a;
    asm("{ .reg .u64 t; cvta.to.shared.u64 t, %1; cvt.u32.u64 %0, t; }" : "=r"(a) : "l"(p));
    return a;
}
__device__ __forceinline__ void cp_async16(uint32_t dst, const void* src) {
    asm volatile("cp.async.cg.shared.global [%0], [%1], 16;" :: "r"(dst), "l"(src));
}
__device__ __forceinline__ void cp_commit() {
    asm volatile("cp.async.commit_group;" ::: "memory");
}
__device__ __forceinline__ void cp_wait0() {
    asm volatile("cp.async.wait_group 0;" ::: "memory");
}
__device__ __forceinline__ void cp_wait1() {
    asm volatile("cp.async.wait_group 1;" ::: "memory");
}

__device__ __forceinline__ void mma_f16(float* d, const uint32_t* a,
                                        uint32_t b0, uint32_t b1)
{
    asm volatile(
        "mma.sync.aligned.m16n8k16.row.col.f32.f16.f16.f32 "
        "{%0,%1,%2,%3}, {%4,%5,%6,%7}, {%8,%9}, {%0,%1,%2,%3};"
        : "+f"(d[0]), "+f"(d[1]), "+f"(d[2]), "+f"(d[3])
        : "r"(a[0]), "r"(a[1]), "r"(a[2]), "r"(a[3]), "r"(b0), "r"(b1));
}
__device__ __forceinline__ void ldsm_x2_t(uint32_t& r0, uint32_t& r1, uint32_t addr)
{
    asm volatile("ldmatrix.sync.aligned.m8n8.x2.trans.shared.b16 {%0,%1}, [%2];"
                 : "=r"(r0), "=r"(r1) : "r"(addr));
}

__device__ __forceinline__ float gelu_exact(float x)
{
    return 0.5f * x * (1.0f + erff(x * 0.70710678118654752f));
}

// ---------------------------------------------------------------------------
// Transpose + convert: Wt[n][k] = half(W[k][n]). Block 32x8, tile 32x32.
// gridDim.z selects among up to 4 weight pairs.
// ---------------------------------------------------------------------------
__global__ __launch_bounds__(256)
void convt(const float* W0, const float* W1, const float* W2, const float* W3,
           __half* T0, __half* T1, __half* T2, __half* T3, int K, int N)
{
    const int z = blockIdx.z;
    const float* W = (z == 0) ? W0 : (z == 1) ? W1 : (z == 2) ? W2 : W3;
    __half*      T = (z == 0) ? T0 : (z == 1) ? T1 : (z == 2) ? T2 : T3;

    __shared__ float tile[32][33];
    const int tx = threadIdx.x, ty = threadIdx.y;
    const int n0 = blockIdx.x * 32, k0 = blockIdx.y * 32;
    #pragma unroll
    for (int j = 0; j < 32; j += 8)
        tile[ty + j][tx] = W[(size_t)(k0 + ty + j) * N + n0 + tx];
    __syncthreads();
    #pragma unroll
    for (int j = 0; j < 32; j += 8)
        T[(size_t)(n0 + ty + j) * K + k0 + tx] = __float2half(tile[tx][ty + j]);
}

// ---------------------------------------------------------------------------
// FP16 tensor-core GEMM: C[M,N] = A[M,K] @ W[K,N] + bias (+gelu) (+res)
// A half [m][k]; B = Wt half [n][k]. 128x128 CTA tile, BK=32, 256 threads
// (8 warps 4x2, warp tile 32x64). 3-stage cp.async pipeline.
// smem strides 40 halves (pad 8) -> all fragment LDS conflict-free.
// Output: half (oh_z) or float (of, with optional residual).
// ---------------------------------------------------------------------------
#define SG_STR 40
#define SG_TILE (128 * SG_STR)                 // halves per tile
#define SMEM_GEMM_BYTES (3 * 2 * SG_TILE * 2)  // 61440 B

__global__ __launch_bounds__(256, 2)
void gemm_h(const __half* __restrict__ A,
            const __half* T0, const __half* T1, const __half* T2,
            const float* b0p, const float* b1p, const float* b2p,
            __half* h0p, __half* h1p, __half* h2p,
            float* of, const float* __restrict__ res,
            int M, int N, int K, int act)
{
    const int z = blockIdx.z;
    const __half* Wt   = (z == 0) ? T0  : (z == 1) ? T1  : T2;
    const float*  bias = (z == 0) ? b0p : (z == 1) ? b1p : b2p;
    __half*       Ch   = (z == 0) ? h0p : (z == 1) ? h1p : h2p;

    extern __shared__ __half smh[];
    __half* sA[3] = { smh,               smh + 2 * SG_TILE, smh + 4 * SG_TILE };
    __half* sB[3] = { smh + SG_TILE,     smh + 3 * SG_TILE, smh + 5 * SG_TILE };
    const uint32_t sA_u[3] = { smem_u32(sA[0]), smem_u32(sA[1]), smem_u32(sA[2]) };
    const uint32_t sB_u[3] = { smem_u32(sB[0]), smem_u32(sB[1]), smem_u32(sB[2]) };

    const int tid  = threadIdx.x;
    const int wid  = tid >> 5;
    const int lane = tid & 31;
    const int g    = lane >> 2;
    const int tq   = lane & 3;
    const int bm = blockIdx.y * 128;
    const int bn = blockIdx.x * 128;
    const int wm = (wid & 3) * 32;
    const int wn = (wid >> 2) * 64;

    float acc[2][8][4];
    #pragma unroll
    for (int ms = 0; ms < 2; ms++)
        #pragma unroll
        for (int ns = 0; ns < 8; ns++)
            #pragma unroll
            for (int i = 0; i < 4; i++) acc[ms][ns][i] = 0.f;

    const int nChunks = K >> 5;

    auto loadAB = [&](int c, int b) {
        const __half* Ab = A + (size_t)bm * K + (c << 5);
        const __half* Bb = Wt + (size_t)bn * K + (c << 5);
        #pragma unroll
        for (int it = 0; it < 2; ++it) {   // 128 rows x 4 segs of 16B
            const int idx = tid + it * 256;
            const int row = idx >> 2;
            const int seg = idx & 3;
            cp_async16(sA_u[b] + (uint32_t)(row * SG_STR * 2 + seg * 16),
                       Ab + (size_t)row * K + seg * 8);
            cp_async16(sB_u[b] + (uint32_t)(row * SG_STR * 2 + seg * 16),
                       Bb + (size_t)row * K + seg * 8);
        }
    };

    auto compute = [&](int b) {
        const __half* pA = sA[b];
        const __half* pB = sB[b];
        #pragma unroll
        for (int kk = 0; kk < 2; kk++) {
            const int kb = kk * 16 + 2 * tq;
            uint32_t a[2][4];
            #pragma unroll
            for (int ms = 0; ms < 2; ms++) {
                const int r0 = wm + ms * 16 + g;
                a[ms][0] = *(const uint32_t*)(pA + r0 * SG_STR + kb);
                a[ms][1] = *(const uint32_t*)(pA + (r0 + 8) * SG_STR + kb);
                a[ms][2] = *(const uint32_t*)(pA + r0 * SG_STR + kb + 8);
                a[ms][3] = *(const uint32_t*)(pA + (r0 + 8) * SG_STR + kb + 8);
            }
            #pragma unroll
            for (int ns = 0; ns < 8; ns++) {
                const int n = wn + ns * 8 + g;
                const uint32_t b0 = *(const uint32_t*)(pB + n * SG_STR + kb);
                const uint32_t b1 = *(const uint32_t*)(pB + n * SG_STR + kb + 8);
                mma_f16(acc[0][ns], a[0], b0, b1);
                mma_f16(acc[1][ns], a[1], b0, b1);
            }
        }
    };

    loadAB(0, 0); cp_commit();
    if (nChunks > 1) { loadAB(1, 1); cp_commit(); }

    for (int c = 0; c < nChunks; ++c) {
        if (c + 1 < nChunks) cp_wait1(); else cp_wait0();
        __syncthreads();
        compute(c % 3);
        if (c + 2 < nChunks) { loadAB(c + 2, (c + 2) % 3); cp_commit(); }
    }

    // Epilogue
    #pragma unroll
    for (int ms = 0; ms < 2; ms++) {
        const int r0 = bm + wm + 16 * ms + g;
        const int r1 = r0 + 8;
        #pragma unroll
        for (int ns = 0; ns < 8; ns++) {
            const int col = bn + wn + 8 * ns + 2 * tq;
            const float2 bb = *(const float2*)(bias + col);
            float o00 = acc[ms][ns][0] + bb.x;
            float o01 = acc[ms][ns][1] + bb.y;
            float o10 = acc[ms][ns][2] + bb.x;
            float o11 = acc[ms][ns][3] + bb.y;
            if (act) {
                o00 = gelu_exact(o00); o01 = gelu_exact(o01);
                o10 = gelu_exact(o10); o11 = gelu_exact(o11);
            }
            if (of) {
                if (res) {
                    const float2 q0 = *(const float2*)(res + (size_t)r0 * N + col);
                    const float2 q1 = *(const float2*)(res + (size_t)r1 * N + col);
                    o00 += q0.x; o01 += q0.y; o10 += q1.x; o11 += q1.y;
                }
                *(float2*)(of + (size_t)r0 * N + col) = make_float2(o00, o01);
                *(float2*)(of + (size_t)r1 * N + col) = make_float2(o10, o11);
            } else {
                *(__half2*)(Ch + (size_t)r0 * N + col) = __floats2half2_rn(o00, o01);
                *(__half2*)(Ch + (size_t)r1 * N + col) = __floats2half2_rn(o10, o11);
            }
        }
    }
}

// ---------------------------------------------------------------------------
// LayerNorm: one block per row of 1024, 256 threads -> half output
// ---------------------------------------------------------------------------
__global__ __launch_bounds__(256)
void ln_kernel(const float* __restrict__ x, const float* __restrict__ w,
               const float* __restrict__ b, __half* __restrict__ out)
{
    const int row = blockIdx.x;
    const int tid = threadIdx.x;
    const float4 v = *(const float4*)(x + (size_t)row * CN_ + tid * 4);

    float s  = v.x + v.y + v.z + v.w;
    float ss = v.x * v.x + v.y * v.y + v.z * v.z + v.w * v.w;
    #pragma unroll
    for (int o = 16; o > 0; o >>= 1) {
        s  += __shfl_xor_sync(0xFFFFFFFFu, s,  o);
        ss += __shfl_xor_sync(0xFFFFFFFFu, ss, o);
    }
    __shared__ float rs[8], rss[8];
    const int wid = tid >> 5, lane = tid & 31;
    if (lane == 0) { rs[wid] = s; rss[wid] = ss; }
    __syncthreads();
    float tot = 0.f, tots = 0.f;
    #pragma unroll
    for (int i = 0; i < 8; i++) { tot += rs[i]; tots += rss[i]; }

    const float mu   = tot * (1.0f / (float)CN_);
    const float var  = tots * (1.0f / (float)CN_) - mu * mu;
    const float rsig = rsqrtf(var + 1e-5f);

    const float4 wv = *(const float4*)(w + tid * 4);
    const float4 bv = *(const float4*)(b + tid * 4);
    const float o0 = (v.x - mu) * rsig * wv.x + bv.x;
    const float o1 = (v.y - mu) * rsig * wv.y + bv.y;
    const float o2 = (v.z - mu) * rsig * wv.z + bv.z;
    const float o3 = (v.w - mu) * rsig * wv.w + bv.w;
    __half2* op = (__half2*)(out + (size_t)row * CN_ + tid * 4);
    op[0] = __floats2half2_rn(o0, o1);
    op[1] = __floats2half2_rn(o2, o3);
}

// ---------------------------------------------------------------------------
// FP16 tensor-core flash attention (causal).
// Block 128 threads (4 warps); tile 64x64, d=64. Q frags in regs (scaled).
// smem half tiles, stride 72 halves. K natural [kv][d]; V via ldmatrix.trans.
// ---------------------------------------------------------------------------
#define AT_STR 72
#define AT_TILE (64 * AT_STR)   // halves
#define SMEM_ATTN_BYTES (5 * AT_TILE * 2)   // QP + 2K + 2V = 46080 B

__global__ __launch_bounds__(128)
void attn_tc(const __half* __restrict__ q, const __half* __restrict__ k,
             const __half* __restrict__ v, __half* __restrict__ out)
{
    extern __shared__ __half smh[];
    __half* sQP   = smh;
    __half* sK[2] = { smh + AT_TILE,     smh + 3 * AT_TILE };
    __half* sV[2] = { smh + 2 * AT_TILE, smh + 4 * AT_TILE };
    const uint32_t sQP_u   = smem_u32(sQP);
    const uint32_t sK_u[2] = { smem_u32(sK[0]), smem_u32(sK[1]) };
    const uint32_t sV_u[2] = { smem_u32(sV[0]), smem_u32(sV[1]) };

    const int qt  = blockIdx.x;
    const int bh  = blockIdx.y;
    const int b   = bh >> 4;
    const int h   = bh & 15;
    const int tid  = threadIdx.x;
    const int wid  = tid >> 5;
    const int lane = tid & 31;
    const int g    = lane >> 2;
    const int tq   = lane & 3;

    const size_t headoff = (size_t)h * DH_;
    const __half* qbase = q + ((size_t)b * TN_ + qt * 64) * CN_ + headoff;

    // Q tile: 64 rows x 8 segs of 16B
    #pragma unroll
    for (int it = 0; it < 4; ++it) {
        const int idx = tid + it * 128;
        const int row = idx >> 3;
        const int seg = idx & 7;
        cp_async16(sQP_u + (uint32_t)(row * AT_STR * 2 + seg * 16),
                   qbase + (size_t)row * CN_ + seg * 8);
    }
    auto loadKV = [&](int kt, int bb) {
        const __half* kb = k + ((size_t)b * TN_ + kt * 64) * CN_ + headoff;
        const __half* vb = v + ((size_t)b * TN_ + kt * 64) * CN_ + headoff;
        #pragma unroll
        for (int it = 0; it < 4; ++it) {
            const int idx = tid + it * 128;
            const int row = idx >> 3;
            const int seg = idx & 7;
            cp_async16(sK_u[bb] + (uint32_t)(row * AT_STR * 2 + seg * 16),
                       kb + (size_t)row * CN_ + seg * 8);
            cp_async16(sV_u[bb] + (uint32_t)(row * AT_STR * 2 + seg * 16),
                       vb + (size_t)row * CN_ + seg * 8);
        }
    };

    loadKV(0, 0);
    cp_commit();
    cp_wait0();
    __syncthreads();

    const int r_in0 = 16 * wid + g;
    const int r_in1 = r_in0 + 8;

    // Q fragments (scale 0.125 folded in; exact in half)
    uint32_t qa[4][4];
    {
        const __half2 sc = __float2half2_rn(0.125f);
        #pragma unroll
        for (int kk = 0; kk < 4; kk++) {
            const int kb = kk * 16 + 2 * tq;
            #pragma unroll
            for (int i = 0; i < 4; i++) {
                const int rr = (i & 1) ? r_in1 : r_in0;
                const int cc = kb + ((i >> 1) ? 8 : 0);
                uint32_t raw = *(const uint32_t*)(sQP + rr * AT_STR + cc);
                __half2 hv = *reinterpret_cast<__half2*>(&raw);
                hv = __hmul2(hv, sc);
                qa[kk][i] = *reinterpret_cast<uint32_t*>(&hv);
            }
        }
    }
    __syncthreads();   // sQP now reusable as sP

    float o[8][4];
    #pragma unroll
    for (int ns = 0; ns < 8; ns++)
        #pragma unroll
        for (int i = 0; i < 4; i++) o[ns][i] = 0.f;
    float m0 = -1e30f, m1 = -1e30f, l0 = 0.f, l1 = 0.f;

    for (int kt = 0; kt <= qt; kt++) {
        const int cur = kt & 1;
        if (kt + 1 <= qt) { loadKV(kt + 1, cur ^ 1); cp_commit(); }
        if (kt + 1 <= qt) cp_wait1(); else cp_wait0();
        __syncthreads();

        // ---- S = Q K^T (B frags direct from K [kv][d]) ----
        float s[8][4];
        #pragma unroll
        for (int ns = 0; ns < 8; ns++)
            #pragma unroll
            for (int i = 0; i < 4; i++) s[ns][i] = 0.f;
        const __half* pK = sK[cur];
        #pragma unroll
        for (int kk = 0; kk < 4; kk++) {
            const int kb = kk * 16 + 2 * tq;
            #pragma unroll
            for (int ns = 0; ns < 8; ns++) {
                const int n = 8 * ns + g;
                const uint32_t b0 = *(const uint32_t*)(pK + n * AT_STR + kb);
                const uint32_t b1 = *(const uint32_t*)(pK + n * AT_STR + kb + 8);
                mma_f16(s[ns], qa[kk], b0, b1);
            }
        }

        // ---- causal mask (diag tile only) ----
        if (kt == qt) {
            #pragma unroll
            for (int ns = 0; ns < 8; ns++) {
                const int c0 = 8 * ns + 2 * tq;
                if (c0     > r_in0) s[ns][0] = -1e30f;
                if (c0 + 1 > r_in0) s[ns][1] = -1e30f;
                if (c0     > r_in1) s[ns][2] = -1e30f;
                if (c0 + 1 > r_in1) s[ns][3] = -1e30f;
            }
        }

        // ---- online softmax ----
        float rm0 = -1e30f, rm1 = -1e30f;
        #pragma unroll
        for (int ns = 0; ns < 8; ns++) {
            rm0 = fmaxf(rm0, fmaxf(s[ns][0], s[ns][1]));
            rm1 = fmaxf(rm1, fmaxf(s[ns][2], s[ns][3]));
        }
        rm0 = fmaxf(rm0, __shfl_xor_sync(0xFFFFFFFFu, rm0, 1));
        rm0 = fmaxf(rm0, __shfl_xor_sync(0xFFFFFFFFu, rm0, 2));
        rm1 = fmaxf(rm1, __shfl_xor_sync(0xFFFFFFFFu, rm1, 1));
        rm1 = fmaxf(rm1, __shfl_xor_sync(0xFFFFFFFFu, rm1, 2));

        const float nm0 = fmaxf(m0, rm0), nm1 = fmaxf(m1, rm1);
        const float a0 = __expf(m0 - nm0), a1 = __expf(m1 - nm1);
        float ps0 = 0.f, ps1 = 0.f;
        #pragma unroll
        for (int ns = 0; ns < 8; ns++) {
            const float p00 = __expf(s[ns][0] - nm0);
            const float p01 = __expf(s[ns][1] - nm0);
            const float p10 = __expf(s[ns][2] - nm1);
            const float p11 = __expf(s[ns][3] - nm1);
            ps0 += p00 + p01;
            ps1 += p10 + p11;
            const int cc = 8 * ns + 2 * tq;
            *(__half2*)(sQP + r_in0 * AT_STR + cc) = __floats2half2_rn(p00, p01);
            *(__half2*)(sQP + r_in1 * AT_STR + cc) = __floats2half2_rn(p10, p11);
        }
        ps0 += __shfl_xor_sync(0xFFFFFFFFu, ps0, 1);
        ps0 += __shfl_xor_sync(0xFFFFFFFFu, ps0, 2);
        ps1 += __shfl_xor_sync(0xFFFFFFFFu, ps1, 1);
        ps1 += __shfl_xor_sync(0xFFFFFFFFu, ps1, 2);
        l0 = l0 * a0 + ps0;  m0 = nm0;
        l1 = l1 * a1 + ps1;  m1 = nm1;
        #pragma unroll
        for (int ns = 0; ns < 8; ns++) {
            o[ns][0] *= a0; o[ns][1] *= a0;
            o[ns][2] *= a1; o[ns][3] *= a1;
        }
        __syncthreads();   // P visible to whole warp? (warp-local rows, but keep tile ordering)

        // ---- O += P V (A=P from smem, B=V via ldmatrix.trans) ----
        #pragma unroll
        for (int kk = 0; kk < 4; kk++) {
            const int kb = kk * 16 + 2 * tq;
            uint32_t pa[4];
            pa[0] = *(const uint32_t*)(sQP + r_in0 * AT_STR + kb);
            pa[1] = *(const uint32_t*)(sQP + r_in1 * AT_STR + kb);
            pa[2] = *(const uint32_t*)(sQP + r_in0 * AT_STR + kb + 8);
            pa[3] = *(const uint32_t*)(sQP + r_in1 * AT_STR + kb + 8);
            #pragma unroll
            for (int ns = 0; ns < 8; ns++) {
                const uint32_t addr = sV_u[cur]
                    + (uint32_t)(((kk * 16 + (lane & 15)) * AT_STR + 8 * ns) * 2);
                uint32_t b0, b1;
                ldsm_x2_t(b0, b1, addr);
                mma_f16(o[ns], pa, b0, b1);
            }
        }
        __syncthreads();   // P reads done before next tile overwrites sQP/sK/sV
    }

    // ---- epilogue ----
    const float inv0 = 1.0f / l0;
    const float inv1 = 1.0f / l1;
    __half* ob0 = out + ((size_t)b * TN_ + qt * 64 + r_in0) * CN_ + headoff;
    __half* ob1 = out + ((size_t)b * TN_ + qt * 64 + r_in1) * CN_ + headoff;
    #pragma unroll
    for (int ns = 0; ns < 8; ns++) {
        const int d = 8 * ns + 2 * tq;
        *(__half2*)(ob0 + d) = __floats2half2_rn(o[ns][0] * inv0, o[ns][1] * inv0);
        *(__half2*)(ob1 + d) = __floats2half2_rn(o[ns][2] * inv1, o[ns][3] * inv1);
    }
}

// ---------------------------------------------------------------------------
// Launch
// ---------------------------------------------------------------------------
extern "C" void kernel_launch(void* const* d_in, const int* in_sizes, int n_in,
                              void* d_out, int out_size)
{
    const float* x    = (const float*)d_in[0];
    const float* ln1w = (const float*)d_in[2];
    const float* ln1b = (const float*)d_in[3];
    const float* ln2w = (const float*)d_in[4];
    const float* ln2b = (const float*)d_in[5];
    const float* wq   = (const float*)d_in[6];
    const float* bq   = (const float*)d_in[7];
    const float* wk   = (const float*)d_in[8];
    const float* bk   = (const float*)d_in[9];
    const float* wv   = (const float*)d_in[10];
    const float* bv   = (const float*)d_in[11];
    const float* wo   = (const float*)d_in[12];
    const float* bo   = (const float*)d_in[13];
    const float* w1   = (const float*)d_in[14];
    const float* b1   = (const float*)d_in[15];
    const float* w2   = (const float*)d_in[16];
    const float* b2   = (const float*)d_in[17];
    float* out = (float*)d_out;

    __half *h, *q, *k, *v, *ctx, *h2, *ff;
    float *x1;
    __half *wqt, *wkt, *wvt, *wot, *w1t, *w2t;
    cudaGetSymbolAddress((void**)&h,   g_h);
    cudaGetSymbolAddress((void**)&q,   g_q);
    cudaGetSymbolAddress((void**)&k,   g_k);
    cudaGetSymbolAddress((void**)&v,   g_v);
    cudaGetSymbolAddress((void**)&ctx, g_ctx);
    cudaGetSymbolAddress((void**)&x1,  g_x1);
    cudaGetSymbolAddress((void**)&h2,  g_h2);
    cudaGetSymbolAddress((void**)&ff,  g_ff);
    cudaGetSymbolAddress((void**)&wqt, g_wqt);
    cudaGetSymbolAddress((void**)&wkt, g_wkt);
    cudaGetSymbolAddress((void**)&wvt, g_wvt);
    cudaGetSymbolAddress((void**)&wot, g_wot);
    cudaGetSymbolAddress((void**)&w1t, g_w1t);
    cudaGetSymbolAddress((void**)&w2t, g_w2t);

    cudaFuncSetAttribute(gemm_h, cudaFuncAttributeMaxDynamicSharedMemorySize,
                         SMEM_GEMM_BYTES);
    cudaFuncSetAttribute(attn_tc, cudaFuncAttributeMaxDynamicSharedMemorySize,
                         SMEM_ATTN_BYTES);

    const dim3 blk(256);
    const dim3 tblk(32, 8);

    // 0. Transpose + convert weights to half
    convt<<<dim3(CN_ / 32, CN_ / 32, 4), tblk>>>(wq, wk, wv, wo,
                                                 wqt, wkt, wvt, wot, CN_, CN_);
    convt<<<dim3(FFD_ / 32, CN_ / 32, 1), tblk>>>(w1, w1, w1, w1,
                                                  w1t, w1t, w1t, w1t, CN_, FFD_);
    convt<<<dim3(CN_ / 32, FFD_ / 32, 1), tblk>>>(w2, w2, w2, w2,
                                                  w2t, w2t, w2t, w2t, FFD_, CN_);

    // 1. LN1 -> half
    ln_kernel<<<MD_, blk>>>(x, ln1w, ln1b, h);

    // 2. QKV projections merged (z=3) -> half
    const dim3 gQKV(CN_ / 128, MD_ / 128, 3);
    gemm_h<<<gQKV, blk, SMEM_GEMM_BYTES>>>(h, wqt, wkt, wvt, bq, bk, bv,
                                           q, k, v, nullptr, nullptr,
                                           MD_, CN_, CN_, 0);

    // 3. Causal flash attention -> ctx half
    const dim3 gA(TN_ / 64, BN_ * HN_);
    attn_tc<<<gA, dim3(128), SMEM_ATTN_BYTES>>>(q, k, v, ctx);

    // 4. Output projection + residual -> x1 fp32
    const dim3 gP(CN_ / 128, MD_ / 128, 1);
    gemm_h<<<gP, blk, SMEM_GEMM_BYTES>>>(ctx, wot, wot, wot, bo, bo, bo,
                                         nullptr, nullptr, nullptr, x1, x,
                                         MD_, CN_, CN_, 0);

    // 5. LN2 -> half
    ln_kernel<<<MD_, blk>>>(x1, ln2w, ln2b, h2);

    // 6. FFN: gelu(h2@w1+b1) -> ff half; ff@w2+b2+x1 -> out fp32
    const dim3 gF1(FFD_ / 128, MD_ / 128, 1);
    gemm_h<<<gF1, blk, SMEM_GEMM_BYTES>>>(h2, w1t, w1t, w1t, b1, b1, b1,
                                          ff, ff, ff, nullptr, nullptr,
                                          MD_, FFD_, CN_, 1);
    gemm_h<<<gP, blk, SMEM_GEMM_BYTES>>>(ff, w2t, w2t, w2t, b2, b2, b2,
                                         nullptr, nullptr, nullptr, out, x1,
                                         MD_, CN_, FFD_, 0);
}